// round 3
// baseline (speedup 1.0000x reference)
#include <cuda_runtime.h>
#include <math.h>

// ---------------------------------------------------------------------------
// Problem constants
// ---------------------------------------------------------------------------
#define BATCH 4
#define SEQ   2048
#define DIM   1024
#define ROWS  (BATCH * SEQ)          // 8192

// ---------------------------------------------------------------------------
// Device scratch (static __device__ arrays — allocation-free per harness rules)
// ---------------------------------------------------------------------------
__device__ float g_q[ROWS * DIM];                 // 33.5 MB
__device__ float g_k[ROWS * DIM];                 // 33.5 MB
__device__ float g_v[ROWS * DIM];                 // 33.5 MB
__device__ float g_s[BATCH * SEQ * SEQ];          // 67 MB (scores / probs)

// ---------------------------------------------------------------------------
// SGEMM: C = alpha * A @ op(B)
//   A: [M,K] row-major, B: [K,N] row-major (TRANS_B=false) or [N,K] (true)
//   BlockTile 128x128, BK=8, 256 threads, 8x8 per-thread microtile.
//   blockIdx.z selects batch via element strides sA/sB/sC.
// ---------------------------------------------------------------------------
#define BM 128
#define BN 128
#define BK 8
#define TM 8
#define TN 8

template <bool TRANS_B>
__global__ __launch_bounds__(256, 2)
void sgemm_kernel(const float* __restrict__ A,
                  const float* __restrict__ B,
                  float* __restrict__ C,
                  int M, int N, int K, float alpha,
                  long long sA, long long sB, long long sC)
{
    __shared__ float As[BK][BM];
    __shared__ float Bs[BK][BN];

    A += (long long)blockIdx.z * sA + (long long)blockIdx.y * BM * K;
    B += (long long)blockIdx.z * sB
         + (TRANS_B ? (long long)blockIdx.x * BN * K : (long long)blockIdx.x * BN);
    C += (long long)blockIdx.z * sC
         + (long long)blockIdx.y * BM * N + (long long)blockIdx.x * BN;

    const int tid = threadIdx.x;
    const int tx  = tid % 16;          // 16 thread-cols * TN(8) = 128
    const int ty  = tid / 16;          // 16 thread-rows * TM(8) = 128

    // A tile loader: 128 rows x 8 cols. Each thread: one float4.
    const int aRow = tid >> 1;                 // 0..127
    const int aCol = (tid & 1) * 4;            // 0 or 4
    // B tile loader (NN): 8 rows x 128 cols.
    const int bRow = tid >> 5;                 // 0..7
    const int bCol = (tid & 31) * 4;           // 0..124

    float acc[TM][TN];
#pragma unroll
    for (int i = 0; i < TM; i++)
#pragma unroll
        for (int j = 0; j < TN; j++) acc[i][j] = 0.0f;

    for (int k0 = 0; k0 < K; k0 += BK) {
        // --- load A tile (transpose into As[k][m]) ---
        float4 av = *reinterpret_cast<const float4*>(A + (long long)aRow * K + k0 + aCol);
        As[aCol + 0][aRow] = av.x;
        As[aCol + 1][aRow] = av.y;
        As[aCol + 2][aRow] = av.z;
        As[aCol + 3][aRow] = av.w;

        // --- load B tile ---
        if (TRANS_B) {
            // B is [N,K]; Bs[k][n] = B[n][k]
            float4 bv = *reinterpret_cast<const float4*>(B + (long long)aRow * K + k0 + aCol);
            Bs[aCol + 0][aRow] = bv.x;
            Bs[aCol + 1][aRow] = bv.y;
            Bs[aCol + 2][aRow] = bv.z;
            Bs[aCol + 3][aRow] = bv.w;
        } else {
            float4 bv = *reinterpret_cast<const float4*>(B + (long long)(k0 + bRow) * N + bCol);
            *reinterpret_cast<float4*>(&Bs[bRow][bCol]) = bv;
        }
        __syncthreads();

#pragma unroll
        for (int kk = 0; kk < BK; kk++) {
            float ra[TM], rb[TN];
            // vector loads from shared
            float4 ra0 = *reinterpret_cast<const float4*>(&As[kk][ty * TM + 0]);
            float4 ra1 = *reinterpret_cast<const float4*>(&As[kk][ty * TM + 4]);
            ra[0]=ra0.x; ra[1]=ra0.y; ra[2]=ra0.z; ra[3]=ra0.w;
            ra[4]=ra1.x; ra[5]=ra1.y; ra[6]=ra1.z; ra[7]=ra1.w;
            float4 rb0 = *reinterpret_cast<const float4*>(&Bs[kk][tx * TN + 0]);
            float4 rb1 = *reinterpret_cast<const float4*>(&Bs[kk][tx * TN + 4]);
            rb[0]=rb0.x; rb[1]=rb0.y; rb[2]=rb0.z; rb[3]=rb0.w;
            rb[4]=rb1.x; rb[5]=rb1.y; rb[6]=rb1.z; rb[7]=rb1.w;
#pragma unroll
            for (int i = 0; i < TM; i++)
#pragma unroll
                for (int j = 0; j < TN; j++)
                    acc[i][j] = fmaf(ra[i], rb[j], acc[i][j]);
        }
        __syncthreads();
    }

    // --- epilogue ---
#pragma unroll
    for (int i = 0; i < TM; i++) {
        float* crow = C + (long long)(ty * TM + i) * N + tx * TN;
        float4 o0, o1;
        o0.x = alpha * acc[i][0]; o0.y = alpha * acc[i][1];
        o0.z = alpha * acc[i][2]; o0.w = alpha * acc[i][3];
        o1.x = alpha * acc[i][4]; o1.y = alpha * acc[i][5];
        o1.z = alpha * acc[i][6]; o1.w = alpha * acc[i][7];
        *reinterpret_cast<float4*>(crow + 0) = o0;
        *reinterpret_cast<float4*>(crow + 4) = o1;
    }
}

// ---------------------------------------------------------------------------
// Row softmax over g_s: ROWS_TOTAL rows of length SEQ (in-place)
// ---------------------------------------------------------------------------
__global__ __launch_bounds__(256)
void softmax_rows_kernel(float* __restrict__ s, int n)
{
    __shared__ float red[256];
    const int tid = threadIdx.x;
    float* p = s + (long long)blockIdx.x * n;

    // pass 1: max
    float m = -INFINITY;
    for (int i = tid; i < n; i += 256) m = fmaxf(m, p[i]);
    red[tid] = m;
    __syncthreads();
    for (int o = 128; o > 0; o >>= 1) {
        if (tid < o) red[tid] = fmaxf(red[tid], red[tid + o]);
        __syncthreads();
    }
    m = red[0];
    __syncthreads();

    // pass 2: exp + sum
    float sum = 0.0f;
    for (int i = tid; i < n; i += 256) {
        float e = expf(p[i] - m);
        p[i] = e;
        sum += e;
    }
    red[tid] = sum;
    __syncthreads();
    for (int o = 128; o > 0; o >>= 1) {
        if (tid < o) red[tid] += red[tid + o];
        __syncthreads();
    }
    float inv = 1.0f / red[0];
    __syncthreads();

    // pass 3: normalize
    for (int i = tid; i < n; i += 256) p[i] *= inv;
}

// ---------------------------------------------------------------------------
// kernel_launch
// ---------------------------------------------------------------------------
extern "C" void kernel_launch(void* const* d_in, const int* in_sizes, int n_in,
                              void* d_out, int out_size)
{
    const float* x  = (const float*)d_in[0];   // [4,2048,1024]
    const float* wq = (const float*)d_in[1];   // [1024,1024]
    const float* wk = (const float*)d_in[2];
    const float* wv = (const float*)d_in[3];
    float* out = (float*)d_out;                // [4,2048,1024]

    void *pq, *pk, *pv, *ps;
    cudaGetSymbolAddress(&pq, g_q);
    cudaGetSymbolAddress(&pk, g_k);
    cudaGetSymbolAddress(&pv, g_v);
    cudaGetSymbolAddress(&ps, g_s);
    float* q = (float*)pq;
    float* k = (float*)pk;
    float* v = (float*)pv;
    float* s = (float*)ps;

    dim3 block(256);

    // 1) QKV projections: [8192,1024] @ [1024,1024]
    {
        dim3 grid(DIM / BN, ROWS / BM, 1);
        sgemm_kernel<false><<<grid, block>>>(x, wq, q, ROWS, DIM, DIM, 1.0f, 0, 0, 0);
        sgemm_kernel<false><<<grid, block>>>(x, wk, k, ROWS, DIM, DIM, 1.0f, 0, 0, 0);
        sgemm_kernel<false><<<grid, block>>>(x, wv, v, ROWS, DIM, DIM, 1.0f, 0, 0, 0);
    }

    // 2) scores = Q @ K^T / sqrt(D), per batch (z)
    {
        dim3 grid(SEQ / BN, SEQ / BM, BATCH);
        const float alpha = 1.0f / 32.0f;  // 1/sqrt(1024)
        sgemm_kernel<true><<<grid, block>>>(
            q, k, s, SEQ, SEQ, DIM, alpha,
            (long long)SEQ * DIM, (long long)SEQ * DIM, (long long)SEQ * SEQ);
    }

    // 3) softmax rows (8192 rows of 2048)
    softmax_rows_kernel<<<ROWS, 256>>>(s, SEQ);

    // 4) out = P @ V, per batch (z)
    {
        dim3 grid(DIM / BN, SEQ / BM, BATCH);
        sgemm_kernel<false><<<grid, block>>>(
            s, v, out, SEQ, DIM, SEQ, 1.0f,
            (long long)SEQ * SEQ, (long long)SEQ * DIM, (long long)SEQ * DIM);
    }
}

// round 7
// speedup vs baseline: 2.2545x; 2.2545x over previous
#include <cuda_runtime.h>
#include <cuda_bf16.h>
#include <math.h>
#include <stdint.h>

// ---------------------------------------------------------------------------
// Problem constants
// ---------------------------------------------------------------------------
#define BATCH 4
#define SEQ   2048
#define DIM   1024
#define ROWS  (BATCH * SEQ)     // 8192
#define K3    (3 * DIM)         // 3072
#define K3P   (3 * SEQ)         // 6144

// ---------------------------------------------------------------------------
// Device scratch (static, allocation-free)
// ---------------------------------------------------------------------------
__device__ __nv_bfloat16 g_ax[(size_t)ROWS * K3];          // split x   [8192,3072]
__device__ __nv_bfloat16 g_bw[3][(size_t)DIM * K3];        // split W^T [1024,3072] x3
__device__ float         g_q [(size_t)ROWS * DIM];
__device__ float         g_k [(size_t)ROWS * DIM];
__device__ float         g_v [(size_t)ROWS * DIM];
__device__ __nv_bfloat16 g_aq[(size_t)ROWS * K3];          // split Q
__device__ __nv_bfloat16 g_bk[(size_t)ROWS * K3];          // split K
__device__ float         g_s [(size_t)BATCH * SEQ * SEQ];  // scores / probs
__device__ __nv_bfloat16 g_ap[(size_t)ROWS * K3P];         // split P   [8192,6144]
__device__ __nv_bfloat16 g_bv[(size_t)BATCH * DIM * K3P];  // split V^T [4,1024,6144]

// ---------------------------------------------------------------------------
// Helpers
// ---------------------------------------------------------------------------
__device__ __forceinline__ uint32_t smem_u32(const void* p) {
    uint32_t a;
    asm("{ .reg .u64 t; cvta.to.shared.u64 t, %1; cvt.u32.u64 %0, t; }" : "=r"(a) : "l"(p));
    return a;
}
__device__ __forceinline__ void cp16(uint32_t dst, const void* src) {
    asm volatile("cp.async.cg.shared.global [%0], [%1], 16;" :: "r"(dst), "l"(src));
}
__device__ __forceinline__ void ldm_x4(uint32_t& r0, uint32_t& r1, uint32_t& r2, uint32_t& r3,
                                       uint32_t addr) {
    asm volatile("ldmatrix.sync.aligned.m8n8.x4.shared.b16 {%0,%1,%2,%3}, [%4];"
                 : "=r"(r0), "=r"(r1), "=r"(r2), "=r"(r3) : "r"(addr));
}
__device__ __forceinline__ void mma16816(float* d, uint32_t a0, uint32_t a1, uint32_t a2,
                                         uint32_t a3, uint32_t b0, uint32_t b1) {
    asm volatile("mma.sync.aligned.m16n8k16.row.col.f32.bf16.bf16.f32 "
                 "{%0,%1,%2,%3}, {%4,%5,%6,%7}, {%8,%9}, {%0,%1,%2,%3};"
                 : "+f"(d[0]), "+f"(d[1]), "+f"(d[2]), "+f"(d[3])
                 : "r"(a0), "r"(a1), "r"(a2), "r"(a3), "r"(b0), "r"(b1));
}

// ---------------------------------------------------------------------------
// GEMM: C[m,n] = alpha * sum_k A[m,k] * B[n,k]   (A,B bf16 K-major; C fp32)
// 128x128 CTA tile, BK=32, 3-stage cp.async, mma.sync m16n8k16 bf16 (HMMA).
// 8 warps = 2(M) x 4(N); warp tile 64x32.
// SMEM pitch: 32 bf16 row padded to 80 bytes -> conflict-free ldmatrix.
// ---------------------------------------------------------------------------
#define GBM 128
#define GBN 128
#define GBK 32
#define APITCH 80u
#define TILE_BYTES (128u * APITCH)          // 10240 per operand
#define STAGE_BYTES (2u * TILE_BYTES)       // 20480
#define NSTAGE 3
#define GEMM_SMEM (NSTAGE * STAGE_BYTES)    // 61440

__device__ __forceinline__ void g_load_stage(const __nv_bfloat16* A, const __nv_bfloat16* B,
                                             int Kp, int kt, int slot, uint32_t sb, int tid)
{
    const __nv_bfloat16* a0 = A + (size_t)kt * GBK;
    const __nv_bfloat16* b0 = B + (size_t)kt * GBK;
    uint32_t ab = sb + (uint32_t)slot * STAGE_BYTES;
    uint32_t bb = ab + TILE_BYTES;
#pragma unroll
    for (int i = 0; i < 2; i++) {          // A: 128 rows x 4 chunks = 512
        int idx = tid + i * 256;
        int r = idx >> 2, c = idx & 3;
        cp16(ab + (uint32_t)r * APITCH + (uint32_t)c * 16u, a0 + (size_t)r * Kp + c * 8);
    }
#pragma unroll
    for (int i = 0; i < 2; i++) {          // B: 128 rows x 4 chunks = 512
        int idx = tid + i * 256;
        int r = idx >> 2, c = idx & 3;
        cp16(bb + (uint32_t)r * APITCH + (uint32_t)c * 16u, b0 + (size_t)r * Kp + c * 8);
    }
    asm volatile("cp.async.commit_group;" ::: "memory");
}

__global__ __launch_bounds__(256, 2)
void gemm_mma(const __nv_bfloat16* __restrict__ A,
              const __nv_bfloat16* __restrict__ B,
              float* __restrict__ C,
              int Kp, int Nld, float alpha,
              long long sA, long long sB, long long sC)
{
    extern __shared__ char smem_raw[];
    uint32_t sb = smem_u32(smem_raw);

    const int tid  = threadIdx.x;
    const int wid  = tid >> 5;
    const int lane = tid & 31;
    const int wm   = wid & 1;          // 2 warps over M
    const int wn   = wid >> 1;         // 4 warps over N
    const int m0   = wm * 64;
    const int n0   = wn * 32;

    A += (long long)blockIdx.z * sA + (long long)blockIdx.y * GBM * Kp;
    B += (long long)blockIdx.z * sB + (long long)blockIdx.x * GBN * Kp;
    C += (long long)blockIdx.z * sC + (long long)blockIdx.y * GBM * Nld
         + (long long)blockIdx.x * GBN;

    // lane-relative ldmatrix offsets (within a stage, k-step added later)
    // A: row = m0 + 16*i + (lane&15), kcol = (lane>>4)*8
    const uint32_t a_lane_off = (uint32_t)(m0 + (lane & 15)) * APITCH
                              + (uint32_t)((lane >> 4) * 8) * 2u;
    // B: row = n0 + (lane&7) + (lane>>4)*8, kcol = ((lane>>3)&1)*8
    const uint32_t b_lane_off = (uint32_t)(n0 + (lane & 7) + ((lane >> 4) * 8)) * APITCH
                              + (uint32_t)(((lane >> 3) & 1) * 8) * 2u;

    float acc[4][4][4];
#pragma unroll
    for (int i = 0; i < 4; i++)
#pragma unroll
        for (int j = 0; j < 4; j++)
#pragma unroll
            for (int r = 0; r < 4; r++) acc[i][j][r] = 0.0f;

    const int KT = Kp / GBK;

    g_load_stage(A, B, Kp, 0, 0, sb, tid);
    g_load_stage(A, B, Kp, 1, 1, sb, tid);

    int slot = 0;
    for (int kt = 0; kt < KT; kt++) {
        asm volatile("cp.async.wait_group 1;" ::: "memory");
        __syncthreads();

        if (kt + 2 < KT)
            g_load_stage(A, B, Kp, kt + 2, (slot + 2) % NSTAGE, sb, tid);
        else
            asm volatile("cp.async.commit_group;" ::: "memory");

        uint32_t abase = sb + (uint32_t)slot * STAGE_BYTES;
        uint32_t bbase = abase + TILE_BYTES;

#pragma unroll
        for (int ks = 0; ks < 2; ks++) {       // two k16 steps per BK=32
            uint32_t koff = (uint32_t)(ks * 16) * 2u;
            uint32_t af[4][4];
#pragma unroll
            for (int i = 0; i < 4; i++)
                ldm_x4(af[i][0], af[i][1], af[i][2], af[i][3],
                       abase + a_lane_off + (uint32_t)(i * 16) * APITCH + koff);
            uint32_t bf[2][4];
#pragma unroll
            for (int j = 0; j < 2; j++)
                ldm_x4(bf[j][0], bf[j][1], bf[j][2], bf[j][3],
                       bbase + b_lane_off + (uint32_t)(j * 16) * APITCH + koff);
#pragma unroll
            for (int i = 0; i < 4; i++) {
#pragma unroll
                for (int j = 0; j < 2; j++) {
                    mma16816(acc[i][2 * j + 0], af[i][0], af[i][1], af[i][2], af[i][3],
                             bf[j][0], bf[j][1]);
                    mma16816(acc[i][2 * j + 1], af[i][0], af[i][1], af[i][2], af[i][3],
                             bf[j][2], bf[j][3]);
                }
            }
        }
        slot = (slot + 1) % NSTAGE;
        __syncthreads();
    }

    // ---- epilogue ----
    const int erow = lane >> 2;
    const int ecol = (lane & 3) * 2;
#pragma unroll
    for (int i = 0; i < 4; i++) {
#pragma unroll
        for (int j = 0; j < 4; j++) {
            int row = m0 + i * 16 + erow;
            int col = n0 + j * 8 + ecol;
            float2 v0, v1;
            v0.x = alpha * acc[i][j][0];
            v0.y = alpha * acc[i][j][1];
            v1.x = alpha * acc[i][j][2];
            v1.y = alpha * acc[i][j][3];
            *reinterpret_cast<float2*>(C + (size_t)row * Nld + col) = v0;
            *reinterpret_cast<float2*>(C + (size_t)(row + 8) * Nld + col) = v1;
        }
    }
}

// ---------------------------------------------------------------------------
// Split conversions: f32 -> bf16 hi/lo, 3x K expansion
//   MODE 0 (A operand):  [hi, lo, hi]
//   MODE 1 (B operand):  [hi, hi, lo]
// ---------------------------------------------------------------------------
__device__ __forceinline__ void store8bf(__nv_bfloat16* p, const __nv_bfloat16* v) {
    uint4 u;
    u.x = ((uint32_t)__bfloat16_as_ushort(v[1]) << 16) | __bfloat16_as_ushort(v[0]);
    u.y = ((uint32_t)__bfloat16_as_ushort(v[3]) << 16) | __bfloat16_as_ushort(v[2]);
    u.z = ((uint32_t)__bfloat16_as_ushort(v[5]) << 16) | __bfloat16_as_ushort(v[4]);
    u.w = ((uint32_t)__bfloat16_as_ushort(v[7]) << 16) | __bfloat16_as_ushort(v[6]);
    *reinterpret_cast<uint4*>(p) = u;
}

template <int MODE>
__global__ __launch_bounds__(256)
void split_kernel(const float* __restrict__ in, __nv_bfloat16* __restrict__ out,
                  int C, long long n8)
{
    long long idx = (long long)blockIdx.x * blockDim.x + threadIdx.x;
    if (idx >= n8) return;
    long long e = idx * 8;
    long long r = e / C;
    int c = (int)(e - r * C);
    const float4* src = reinterpret_cast<const float4*>(in + e);
    float4 v0 = src[0], v1 = src[1];
    float xs[8] = {v0.x, v0.y, v0.z, v0.w, v1.x, v1.y, v1.z, v1.w};
    __nv_bfloat16 hi[8], lo[8];
#pragma unroll
    for (int j = 0; j < 8; j++) {
        hi[j] = __float2bfloat16_rn(xs[j]);
        lo[j] = __float2bfloat16_rn(xs[j] - __bfloat162float(hi[j]));
    }
    __nv_bfloat16* o = out + r * (long long)(3 * C) + c;
    store8bf(o, hi);
    store8bf(o + C, MODE == 0 ? lo : hi);
    store8bf(o + 2 * C, MODE == 0 ? hi : lo);
}

// Transpose + split: in f32 [z][K][N] -> out bf16 [z][N][3K] = [hi, hi, lo]
__global__ __launch_bounds__(256)
void tsplit_kernel(const float* __restrict__ in, __nv_bfloat16* __restrict__ out,
                   int K, int N)
{
    __shared__ float tile[32][33];
    const float* inz = in + (long long)blockIdx.z * K * N;
    __nv_bfloat16* outz = out + (long long)blockIdx.z * N * (long long)(3 * K);
    int k0 = blockIdx.y * 32, n0 = blockIdx.x * 32;
    int tx = threadIdx.x & 31, ty = threadIdx.x >> 5;
#pragma unroll
    for (int i = ty; i < 32; i += 8)
        tile[i][tx] = inz[(long long)(k0 + i) * N + n0 + tx];
    __syncthreads();
#pragma unroll
    for (int i = ty; i < 32; i += 8) {
        int n = n0 + i, k = k0 + tx;
        float x = tile[tx][i];
        __nv_bfloat16 hi = __float2bfloat16_rn(x);
        __nv_bfloat16 lo = __float2bfloat16_rn(x - __bfloat162float(hi));
        __nv_bfloat16* o = outz + (long long)n * (3 * K) + k;
        o[0] = hi; o[K] = hi; o[2 * K] = lo;
    }
}

// ---------------------------------------------------------------------------
// Row softmax, in place (rows of length SEQ)
// ---------------------------------------------------------------------------
__global__ __launch_bounds__(256)
void softmax_rows_kernel(float* __restrict__ s, int n)
{
    __shared__ float red[256];
    const int tid = threadIdx.x;
    float* p = s + (long long)blockIdx.x * n;

    float m = -INFINITY;
    for (int i = tid; i < n; i += 256) m = fmaxf(m, p[i]);
    red[tid] = m;
    __syncthreads();
    for (int o = 128; o > 0; o >>= 1) {
        if (tid < o) red[tid] = fmaxf(red[tid], red[tid + o]);
        __syncthreads();
    }
    m = red[0];
    __syncthreads();

    float sum = 0.0f;
    for (int i = tid; i < n; i += 256) {
        float e = expf(p[i] - m);
        p[i] = e;
        sum += e;
    }
    red[tid] = sum;
    __syncthreads();
    for (int o = 128; o > 0; o >>= 1) {
        if (tid < o) red[tid] += red[tid + o];
        __syncthreads();
    }
    float inv = 1.0f / red[0];
    __syncthreads();
    for (int i = tid; i < n; i += 256) p[i] *= inv;
}

// ---------------------------------------------------------------------------
// kernel_launch
// ---------------------------------------------------------------------------
extern "C" void kernel_launch(void* const* d_in, const int* in_sizes, int n_in,
                              void* d_out, int out_size)
{
    const float* x  = (const float*)d_in[0];
    const float* wq = (const float*)d_in[1];
    const float* wk = (const float*)d_in[2];
    const float* wv = (const float*)d_in[3];
    float* out = (float*)d_out;

    void *pax, *pbw, *pq, *pk, *pv, *paq, *pbk, *ps, *pap, *pbv;
    cudaGetSymbolAddress(&pax, g_ax);
    cudaGetSymbolAddress(&pbw, g_bw);
    cudaGetSymbolAddress(&pq, g_q);
    cudaGetSymbolAddress(&pk, g_k);
    cudaGetSymbolAddress(&pv, g_v);
    cudaGetSymbolAddress(&paq, g_aq);
    cudaGetSymbolAddress(&pbk, g_bk);
    cudaGetSymbolAddress(&ps, g_s);
    cudaGetSymbolAddress(&pap, g_ap);
    cudaGetSymbolAddress(&pbv, g_bv);

    __nv_bfloat16* ax = (__nv_bfloat16*)pax;
    __nv_bfloat16* bw = (__nv_bfloat16*)pbw;
    float* q = (float*)pq;
    float* k = (float*)pk;
    float* v = (float*)pv;
    __nv_bfloat16* aq = (__nv_bfloat16*)paq;
    __nv_bfloat16* bk = (__nv_bfloat16*)pbk;
    float* s = (float*)ps;
    __nv_bfloat16* ap = (__nv_bfloat16*)pap;
    __nv_bfloat16* bv = (__nv_bfloat16*)pbv;

    cudaFuncSetAttribute(gemm_mma, cudaFuncAttributeMaxDynamicSharedMemorySize, GEMM_SMEM);

    // 1) split x -> A operand [8192, 3072]
    {
        long long n8 = (long long)ROWS * DIM / 8;
        split_kernel<0><<<(unsigned)((n8 + 255) / 256), 256>>>(x, ax, DIM, n8);
    }
    // 2) transpose+split weights -> B operands [1024, 3072]
    {
        dim3 g(DIM / 32, DIM / 32, 1);
        tsplit_kernel<<<g, 256>>>(wq, bw + 0 * (size_t)DIM * K3, DIM, DIM);
        tsplit_kernel<<<g, 256>>>(wk, bw + 1 * (size_t)DIM * K3, DIM, DIM);
        tsplit_kernel<<<g, 256>>>(wv, bw + 2 * (size_t)DIM * K3, DIM, DIM);
    }
    // 3) Q/K/V projections: [8192,3072] x [1024,3072]^T -> fp32 [8192,1024]
    {
        dim3 g(DIM / GBN, ROWS / GBM, 1);   // (8, 64, 1)
        gemm_mma<<<g, 256, GEMM_SMEM>>>(ax, bw + 0 * (size_t)DIM * K3, q, K3, DIM, 1.0f, 0, 0, 0);
        gemm_mma<<<g, 256, GEMM_SMEM>>>(ax, bw + 1 * (size_t)DIM * K3, k, K3, DIM, 1.0f, 0, 0, 0);
        gemm_mma<<<g, 256, GEMM_SMEM>>>(ax, bw + 2 * (size_t)DIM * K3, v, K3, DIM, 1.0f, 0, 0, 0);
    }
    // 4) split Q (A-mode) and K (B-mode)
    {
        long long n8 = (long long)ROWS * DIM / 8;
        split_kernel<0><<<(unsigned)((n8 + 255) / 256), 256>>>(q, aq, DIM, n8);
        split_kernel<1><<<(unsigned)((n8 + 255) / 256), 256>>>(k, bk, DIM, n8);
    }
    // 5) scores = Q K^T / 32 per batch: [2048,3072] x [2048,3072]^T
    {
        dim3 g(SEQ / GBN, SEQ / GBM, BATCH);   // (16, 16, 4)
        gemm_mma<<<g, 256, GEMM_SMEM>>>(aq, bk, s, K3, SEQ, 1.0f / 32.0f,
                                        (long long)SEQ * K3, (long long)SEQ * K3,
                                        (long long)SEQ * SEQ);
    }
    // 6) softmax
    softmax_rows_kernel<<<ROWS, 256>>>(s, SEQ);

    // 7) split P (A-mode) [8192, 6144]; transpose+split V -> [4,1024,6144]
    {
        long long n8 = (long long)ROWS * SEQ / 8;
        split_kernel<0><<<(unsigned)((n8 + 255) / 256), 256>>>(s, ap, SEQ, n8);
        dim3 g(DIM / 32, SEQ / 32, BATCH);
        tsplit_kernel<<<g, 256>>>(v, bv, SEQ, DIM);
    }
    // 8) out = P V per batch: [2048,6144] x [1024,6144]^T -> fp32 [2048,1024]
    {
        dim3 g(DIM / GBN, SEQ / GBM, BATCH);   // (8, 16, 4)
        gemm_mma<<<g, 256, GEMM_SMEM>>>(ap, bv, out, K3P, DIM, 1.0f,
                                        (long long)SEQ * K3P, (long long)DIM * K3P,
                                        (long long)SEQ * DIM);
    }
}